// round 13
// baseline (speedup 1.0000x reference)
#include <cuda_runtime.h>
#include <math.h>

#define TT     4096
#define NTHR   384
#define GRIDN  144            // 9 batches x 16: A(0-3) B2(4-7) B1(8-11) C(12) idle(13-15)
#define SMEMB  139264

typedef unsigned u32;

// L2 rings (cross-stage), batch-partitioned
__device__ float g_h1[9][8][512];
__device__ float g_h2[9][8][512];
__device__ float g_p1[9][8][512];
__device__ float g_fb[9][8][16];       // m[0..5], pos[6..7], vel[8..9]
__device__ u32   g_cnt[9 * 512];       // per batch: c_h1@0 c_h2@32 c_m@64 c_p1[i]@96+32i

__device__ __forceinline__ u32 ldacq(const u32* p) {
    u32 v;
    asm volatile("ld.acquire.gpu.global.u32 %0, [%1];" : "=r"(v) : "l"(p));
    return v;
}
__device__ __forceinline__ void redrel(u32* p) {
    asm volatile("red.release.gpu.global.add.u32 [%0], 1;" :: "l"(p));
}

// ---- cluster / DSMEM helpers ----
__device__ __forceinline__ u32 smem_u32(const void* p) {
    u32 a;
    asm("{ .reg .u64 t; cvta.to.shared.u64 t, %1; cvt.u32.u64 %0, t; }"
        : "=r"(a) : "l"(p));
    return a;
}
__device__ __forceinline__ u32 mapa_rk(u32 a, u32 rk) {
    u32 d;
    asm("mapa.shared::cluster.u32 %0, %1, %2;" : "=r"(d) : "r"(a), "r"(rk));
    return d;
}
__device__ __forceinline__ void stsc(u32 a, float v) {
    asm volatile("st.shared::cluster.f32 [%0], %1;" :: "r"(a), "f"(v) : "memory");
}
__device__ __forceinline__ void mbar_init(u32 a, u32 cnt) {
    asm volatile("mbarrier.init.shared.b64 [%0], %1;" :: "r"(a), "r"(cnt) : "memory");
}
__device__ __forceinline__ void mbar_arrive_rk(u32 a, u32 rk) {
    u32 r = mapa_rk(a, rk);
    asm volatile("mbarrier.arrive.shared::cluster.b64 _, [%0];" :: "r"(r) : "memory");
}
__device__ __forceinline__ void mbar_wait(u32 a, u32 par) {
    u32 done;
    asm volatile(
        "{\n\t.reg .pred p;\n\t"
        "mbarrier.try_wait.parity.acquire.cluster.shared::cta.b64 p, [%1], %2;\n\t"
        "selp.b32 %0, 1, 0, p;\n\t}"
        : "=r"(done) : "r"(a), "r"(par) : "memory");
    while (!done) {
        asm volatile(
            "{\n\t.reg .pred p;\n\t"
            "mbarrier.try_wait.parity.acquire.cluster.shared::cta.b64 p, [%1], %2, 0x989680;\n\t"
            "selp.b32 %0, 1, 0, p;\n\t}"
            : "=r"(done) : "r"(a), "r"(par) : "memory");
    }
}
__device__ __forceinline__ void fence_cluster() {
    asm volatile("fence.acq_rel.cluster;" ::: "memory");
}
#define CLUSTER_SYNC() do { \
    asm volatile("barrier.cluster.arrive.aligned;" ::: "memory"); \
    asm volatile("barrier.cluster.wait.aligned;"   ::: "memory"); } while (0)

template <int N>
__device__ __forceinline__ void bfly(float* a) {
    #pragma unroll
    for (int o = 16; o; o >>= 1)
        #pragma unroll
        for (int q = 0; q < N; q++) a[q] += __shfl_xor_sync(0xffffffffu, a[q], o);
}
template <int N>
__device__ __forceinline__ float sel(const float* a, int lane) {
    float v = 0.f;
    #pragma unroll
    for (int q = 0; q < N; q++) if (lane == q) v = a[q];
    return v;
}
__device__ __forceinline__ float dot4(float4 w, float4 x) {
    return w.x * x.x + w.y * x.y + w.z * x.z + w.w * x.w;
}

// 11-row GEMV: chunks 0-1 of W in regs, chunks 2-3 in SMEM (pitch 256 floats).
__device__ __forceinline__ float gemv11(const float4 wreg[11][2], const float* Wsm,
                                        int rbase, int lane,
                                        float4 x0, float4 x1, float4 x2, float4 x3) {
    float acc[11];
    #pragma unroll
    for (int r = 0; r < 11; r++) {
        int rl = rbase + r; if (rl > 124) rl = 124;
        const float4* wr = (const float4*)(Wsm + rl * 256);
        acc[r] = dot4(wreg[r][0], x0) + dot4(wreg[r][1], x1)
               + dot4(wr[lane], x2)   + dot4(wr[32 + lane], x3);
    }
    bfly<11>(acc);
    return sel<11>(acc, lane);
}

__device__ __forceinline__ void loadw11(float4 wreg[11][2], const float* Wsrc,
                                        int r0, int rbase, int lane) {
    #pragma unroll
    for (int r = 0; r < 11; r++) {
        int rl = rbase + r; if (rl > 124) rl = 124;
        const float* wp = Wsrc + (size_t)(r0 + rl) * 500;
        wreg[r][0] = *(const float4*)(wp + 4 * lane);         // cols 0..127
        wreg[r][1] = *(const float4*)(wp + 128 + 4 * lane);   // cols 128..255
    }
}

// SMEM float layout: XB0 0..511 | XB1 512..1023 | mbar 1024..1025 |
// AUX 1040..1103 | bias 1104..1231 | Win_s 1232..2731 | W 2752..34751
__global__ void __launch_bounds__(NTHR, 1) __cluster_dims__(4, 1, 1)
ctrl_kernel(const float* __restrict__ pert,
            const float* __restrict__ n1g,  const float* __restrict__ n2g,
            const float* __restrict__ nmg,  const float* __restrict__ home,
            const float* __restrict__ Win,  const float* __restrict__ bin,
            const float* __restrict__ Wsf1, const float* __restrict__ Wout,
            const float* __restrict__ bout, const float* __restrict__ Wsf2,
            const float* __restrict__ Wmus, const float* __restrict__ Marm,
            float* __restrict__ out)
{
    extern __shared__ float sm[];
    float* XB0   = sm;
    float* XB1   = sm + 512;
    float* AUX   = sm + 1040;
    float* bias  = sm + 1104;
    float* Win_s = sm + 1232;
    float* W     = sm + 2752;

    const int tid  = threadIdx.x;
    const int lane = tid & 31;
    const int wrp  = tid >> 5;
    const int bid  = blockIdx.x;
    const int g    = bid >> 4;
    const int loc  = bid & 15;
    const int b    = g;
    const u32 rank = (u32)(bid & 3);

    if (loc >= 13) return;            // idle CTAs (cluster 3 has no cluster ops)

    u32* cb   = &g_cnt[g * 512];
    u32* c_h1 = cb;
    u32* c_h2 = cb + 32;
    u32* c_m  = cb + 64;

    const int rbase = (wrp * 125) / 12;
    const int nr    = ((wrp + 1) * 125) / 12 - rbase;
    const int lrow  = rbase + lane;                // local row if lane<nr
    const u32 mbar  = smem_u32(sm + 1024);

    if (loc < 4) {
        // ============================ A: h1 (DSMEM cluster) ================
        const int r0 = (int)rank * 125;
        const float h0 = home[b * 2], h1v = home[b * 2 + 1];
        float4 wreg[11][2];
        loadw11(wreg, Wsf1, r0, rbase, lane);
        for (int i = tid; i < 32000; i += NTHR) {       // W chunks 2,3
            int r = i >> 8, c = i & 255, col = 256 + c;
            W[i] = (col < 500) ? Wsf1[(size_t)(r0 + r) * 500 + col] : 0.f;
        }
        for (int i = tid; i < 1500; i += NTHR)
            Win_s[i] = Win[(r0 + i / 12) * 12 + (i % 12)];
        for (int i = tid; i < 125; i += NTHR) bias[i] = bin[r0 + i];
        for (int i = tid; i < 1024; i += NTHR) sm[i] = 0.f;   // zero xbufs
        if (tid == 0) mbar_init(mbar, 4);
        __syncthreads();
        CLUSTER_SYNC();

        // gen 0: h1(0) = tanh(b_in)
        if (lane < nr) {
            float v = tanhf(bias[lrow]);
            u32 la = smem_u32(XB0 + r0 + lrow);
            #pragma unroll
            for (u32 rk = 0; rk < 4; rk++) stsc(mapa_rk(la, rk), v);
            g_h1[g][0][r0 + lrow] = v;
        }
        __syncthreads();
        if (tid == 0) {
            fence_cluster();
            #pragma unroll
            for (u32 rk = 0; rk < 4; rk++) mbar_arrive_rk(mbar, rk);
            redrel(c_h1);
        }

        for (int t = 1; t < TT; ++t) {
            float nse = 0.f;
            if (lane < nr)
                nse = n1g[(size_t)(t - 1) * 4500 + b * 500 + (r0 + lrow)];

            if (tid == 0) {
                int tm = t - 6; if (tm < 0) tm = 0;
                while (ldacq(c_m) < (u32)(tm + 1)) { }
            }
            mbar_wait(mbar, (u32)((t - 1) & 1));
            __syncthreads();

            int t6 = t - 6; if (t6 < 0) t6 = 0;
            if (tid < 12) {
                const float* fb = g_fb[g][t6 & 7];
                int c = tid;
                float v = 0.f;
                if (c >= 2 && c < 4)
                    v = 2.0f * (__ldcg(fb + 6 + (c - 2)) - ((c == 2) ? h0 : h1v));
                else if (c >= 4 && c < 6) v = 0.5f * __ldcg(fb + 8 + (c - 4));
                else if (c >= 6)          v = __ldcg(fb + (c - 6));
                AUX[c] = v;
            }

            const float* xb = ((t - 1) & 1) ? XB1 : XB0;
            float4 x0 = *(const float4*)(xb + 4 * lane);
            float4 x1 = *(const float4*)(xb + 128 + 4 * lane);
            float4 x2 = *(const float4*)(xb + 256 + 4 * lane);
            float4 x3 = *(const float4*)(xb + 384 + 4 * lane);
            float hp = 0.f;
            if (lane < nr) hp = xb[r0 + lrow];

            float v = gemv11(wreg, W, rbase, lane, x0, x1, x2, x3);
            __syncthreads();                        // AUX visible

            if (lane < nr) {
                const float* wi = Win_s + lrow * 12;
                float pre = v + bias[lrow];
                #pragma unroll
                for (int c = 2; c < 12; c++) pre += wi[c] * AUX[c];
                float val = 0.5f * tanhf(pre) + 0.5f * hp + nse * hp * hp;
                float* xw = (t & 1) ? XB1 : XB0;
                u32 la = smem_u32(xw + r0 + lrow);
                #pragma unroll
                for (u32 rk = 0; rk < 4; rk++) stsc(mapa_rk(la, rk), val);
                g_h1[g][t & 7][r0 + lrow] = val;
            }
            __syncthreads();
            if (tid == 0) {
                fence_cluster();
                #pragma unroll
                for (u32 rk = 0; rk < 4; rk++) mbar_arrive_rk(mbar, rk);
                redrel(c_h1);
            }
        }
        CLUSTER_SYNC();
    } else if (loc < 8) {
        // ============================ B2: h2 (DSMEM cluster) ===============
        const int r0 = (int)rank * 125;
        u32* c_p1 = cb + 96 + 32 * (int)rank;
        float4 wreg[11][2];
        loadw11(wreg, Wsf2, r0, rbase, lane);
        for (int i = tid; i < 32000; i += NTHR) {
            int r = i >> 8, c = i & 255, col = 256 + c;
            W[i] = (col < 500) ? Wsf2[(size_t)(r0 + r) * 500 + col] : 0.f;
        }
        for (int i = tid; i < 125; i += NTHR) bias[i] = bout[r0 + i];
        for (int i = tid; i < 1024; i += NTHR) sm[i] = 0.f;
        if (tid == 0) mbar_init(mbar, 4);
        __syncthreads();
        CLUSTER_SYNC();

        for (int t = 0; t < TT; ++t) {
            float nse = 0.f;
            if (t >= 1 && lane < nr)
                nse = n2g[(size_t)(t - 1) * 4500 + b * 500 + (r0 + lrow)];

            if (tid == 0) {
                while (ldacq(c_p1) < (u32)(t + 1)) { }
            }
            if (t >= 1) mbar_wait(mbar, (u32)((t - 1) & 1));
            __syncthreads();

            const float* xb = ((t - 1) & 1) ? XB1 : XB0;   // t=0 -> XB1 zeros
            float4 x0 = *(const float4*)(xb + 4 * lane);
            float4 x1 = *(const float4*)(xb + 128 + 4 * lane);
            float4 x2 = *(const float4*)(xb + 256 + 4 * lane);
            float4 x3 = *(const float4*)(xb + 384 + 4 * lane);
            float par = 0.f, hp = 0.f;
            if (lane < nr) {
                par = __ldcg(&g_p1[g][t & 7][r0 + lrow]);
                hp  = xb[r0 + lrow];
            }

            float v = gemv11(wreg, W, rbase, lane, x0, x1, x2, x3);
            if (lane < nr) {
                float pre = v + par + bias[lrow];
                float val = (t == 0) ? tanhf(pre)
                          : 0.5f * tanhf(pre) + 0.5f * hp + nse * hp * hp;
                float* xw = (t & 1) ? XB1 : XB0;
                u32 la = smem_u32(xw + r0 + lrow);
                #pragma unroll
                for (u32 rk = 0; rk < 4; rk++) stsc(mapa_rk(la, rk), val);
                g_h2[g][t & 7][r0 + lrow] = val;
            }
            __syncthreads();
            if (tid == 0) {
                fence_cluster();
                #pragma unroll
                for (u32 rk = 0; rk < 4; rk++) mbar_arrive_rk(mbar, rk);
                redrel(c_h2);
            }
        }
        CLUSTER_SYNC();
    } else if (loc < 12) {
        // ============================ B1: Wout @ h1 (L2, off-critical) =====
        const int i1 = bid & 3;
        const int r0 = i1 * 125;
        u32* c_p1 = cb + 96 + 32 * i1;
        float4 wreg[11][2];
        loadw11(wreg, Wout, r0, rbase, lane);
        for (int i = tid; i < 32000; i += NTHR) {
            int r = i >> 8, c = i & 255, col = 256 + c;
            W[i] = (col < 500) ? Wout[(size_t)(r0 + r) * 500 + col] : 0.f;
        }
        __syncthreads();

        for (int t = 0; t < TT; ++t) {
            if (tid == 0) {
                while (ldacq(c_h1) < 4u * (u32)(t + 1)) { }
            }
            __syncthreads();

            const float4* Xr = (const float4*)g_h1[g][t & 7];
            float4 x0 = __ldcg(Xr + lane);
            float4 x1 = __ldcg(Xr + lane + 32);
            float4 x2 = __ldcg(Xr + lane + 64);
            float4 x3 = __ldcg(Xr + lane + 96);

            float v = gemv11(wreg, W, rbase, lane, x0, x1, x2, x3);
            if (lane < nr)
                g_p1[g][t & 7][r0 + lrow] = v;
            __syncthreads();
            if (tid == 0) redrel(c_p1);
        }
    } else {
        // ============================ C: muscles + arm (loc == 12) =========
        for (int i = tid; i < 6 * 512; i += NTHR) {
            int r = i >> 9, k = i & 511;
            W[i] = (k < 500) ? Wmus[r * 500 + k] : 0.f;
        }
        if (tid < 12) AUX[32 + tid] = Marm[tid];
        if (tid < 2)  AUX[48 + tid] = home[b * 2 + tid];
        __syncthreads();
        if (wrp != 0) return;

        const float4* Wv = (const float4*)W;
        for (int t = 0; t < TT; ++t) {
            float nse = 0.f, pse = 0.f;
            if (t >= 1) {
                if (lane < 6) nse = nmg[(size_t)(t - 1) * 54 + b * 6 + lane];
                if (lane < 2) pse = pert[(size_t)(t - 1) * 18 + b * 2 + lane];
            }

            if (lane == 0) {
                while (ldacq(c_h2) < 4u * (u32)(t + 1)) { }
            }
            __syncwarp();

            const float4* Xr = (const float4*)g_h2[g][t & 7];
            float4 xs[4];
            #pragma unroll
            for (int it = 0; it < 4; ++it) xs[it] = __ldcg(Xr + lane + 32 * it);
            float acc[6];
            #pragma unroll
            for (int r = 0; r < 6; r++) acc[r] = 0.f;
            #pragma unroll
            for (int it = 0; it < 4; ++it) {
                int ch = lane + 32 * it;
                #pragma unroll
                for (int r = 0; r < 6; r++)
                    acc[r] += dot4(Wv[r * 128 + ch], xs[it]);
            }
            bfly<6>(acc);
            float v = sel<6>(acc, lane);
            if (lane < 6) {
                float dot = fmaxf(v, 0.f);
                float mv;
                if (t == 0) {
                    mv = dot;
                } else {
                    float mp = AUX[8 + lane];
                    mv = 0.2f * dot + 0.8f * mp + nse * mp * mp;
                }
                AUX[8 + lane] = mv;
                g_fb[g][t & 7][lane] = mv;
            }
            __syncwarp();
            if (lane < 2) {
                int d = lane;
                float pos, vel;
                if (t == 0) {
                    pos = AUX[48 + d];
                    vel = 0.f;
                } else {
                    float tq = pse;
                    #pragma unroll
                    for (int j = 0; j < 6; j++)
                        tq += AUX[8 + j] * AUX[32 + j * 2 + d];
                    vel = AUX[2 + d] + 0.01f * tq;
                    pos = AUX[0 + d] + 0.01f * vel;
                }
                AUX[0 + d] = pos;
                AUX[2 + d] = vel;
                out[t * 36 + b * 4 + d]     = pos;
                out[t * 36 + b * 4 + 2 + d] = vel;
                g_fb[g][t & 7][6 + d] = pos;
                g_fb[g][t & 7][8 + d] = vel;
            }
            __syncwarp();
            if (lane == 0) redrel(c_m);
        }
    }
}

extern "C" void kernel_launch(void* const* d_in, const int* in_sizes, int n_in,
                              void* d_out, int out_size) {
    // 0 des_targ (dead: scaled by 0), 1 perturb_seq, 2 noise_h1, 3 noise_h2,
    // 4 noise_m, 5 home, 6 W_in, 7 b_in, 8 W_in_self, 9 W_out, 10 b_out,
    // 11 W_out_self, 12 W_mus, 13 M_arm
    const float* pert = (const float*)d_in[1];
    const float* n1g  = (const float*)d_in[2];
    const float* n2g  = (const float*)d_in[3];
    const float* nmg  = (const float*)d_in[4];
    const float* home = (const float*)d_in[5];
    const float* Win  = (const float*)d_in[6];
    const float* bin  = (const float*)d_in[7];
    const float* Wsf1 = (const float*)d_in[8];
    const float* Wout = (const float*)d_in[9];
    const float* bout = (const float*)d_in[10];
    const float* Wsf2 = (const float*)d_in[11];
    const float* Wmus = (const float*)d_in[12];
    const float* Marm = (const float*)d_in[13];
    float* out = (float*)d_out;

    void *p;
    cudaGetSymbolAddress(&p, g_h1);  cudaMemsetAsync(p, 0, sizeof(g_h1),  0);
    cudaGetSymbolAddress(&p, g_h2);  cudaMemsetAsync(p, 0, sizeof(g_h2),  0);
    cudaGetSymbolAddress(&p, g_p1);  cudaMemsetAsync(p, 0, sizeof(g_p1),  0);
    cudaGetSymbolAddress(&p, g_fb);  cudaMemsetAsync(p, 0, sizeof(g_fb),  0);
    cudaGetSymbolAddress(&p, g_cnt); cudaMemsetAsync(p, 0, sizeof(g_cnt), 0);

    cudaFuncSetAttribute(ctrl_kernel,
                         cudaFuncAttributeMaxDynamicSharedMemorySize, SMEMB);

    ctrl_kernel<<<GRIDN, NTHR, SMEMB, 0>>>(pert, n1g, n2g, nmg, home,
                                           Win, bin, Wsf1, Wout, bout,
                                           Wsf2, Wmus, Marm, out);
}

// round 14
// speedup vs baseline: 1.0053x; 1.0053x over previous
#include <cuda_runtime.h>
#include <math.h>

#define TT     4096
#define NTHR   384
#define GRIDN  144            // 9 batches x (A:5, B1:5, B2:5, C:1)
#define SMEMB  212416

typedef unsigned u32;

// depth-8 L2 rings, batch-partitioned
__device__ float g_h1[9][8][512];
__device__ float g_h2[9][8][512];
__device__ float g_p1[9][8][512];   // B1 partials (Wout @ h1)
__device__ float g_fb[9][8][16];    // m[0..5], pos[6..7], vel[8..9]
// one counter per 128B line: [batch][counter][pad]
// 0=c_h1a(A self) 1=c_h1b(B1) 2=c_h2a(B2 self) 3=c_h2c(C) 4=c_m 5..9=c_p1[i]
__device__ u32   g_cnt[9][16][32];

__device__ __forceinline__ u32 ldacq(const u32* p) {
    u32 v;
    asm volatile("ld.acquire.gpu.global.u32 %0, [%1];" : "=r"(v) : "l"(p));
    return v;
}
__device__ __forceinline__ void redrel(u32* p) {
    asm volatile("red.release.gpu.global.add.u32 [%0], 1;" :: "l"(p));
}

template <int N>
__device__ __forceinline__ void bfly(float* a) {
    #pragma unroll
    for (int o = 16; o; o >>= 1)
        #pragma unroll
        for (int q = 0; q < N; q++) a[q] += __shfl_xor_sync(0xffffffffu, a[q], o);
}
template <int N>
__device__ __forceinline__ float sel(const float* a, int lane) {
    float v = 0.f;
    #pragma unroll
    for (int q = 0; q < N; q++) if (lane == q) v = a[q];
    return v;
}

__device__ __forceinline__ float dot4(float4 w, float4 x) {
    return w.x * x.x + w.y * x.y + w.z * x.z + w.w * x.w;
}

// 9-row GEMV, 3/4 of W in registers, chunk 3 from SMEM. X in registers.
__device__ __forceinline__ float gemv_rw(const float4 wreg[9][3], const float4* Wv,
                                         int rbase, int lane,
                                         float4 x0, float4 x1, float4 x2, float4 x3) {
    float acc[9];
    #pragma unroll
    for (int r = 0; r < 9; r++) {
        int rl = rbase + r; if (rl > 99) rl = 99;
        float4 w3 = Wv[rl * 128 + lane + 96];
        acc[r] = dot4(wreg[r][0], x0) + dot4(wreg[r][1], x1)
               + dot4(wreg[r][2], x2) + dot4(w3, x3);
    }
    bfly<9>(acc);
    return sel<9>(acc, lane);
}

__global__ void __launch_bounds__(NTHR, 1)
ctrl_kernel(const float* __restrict__ pert,
            const float* __restrict__ n1g,  const float* __restrict__ n2g,
            const float* __restrict__ nmg,  const float* __restrict__ home,
            const float* __restrict__ Win,  const float* __restrict__ bin,
            const float* __restrict__ Wsf1, const float* __restrict__ Wout,
            const float* __restrict__ bout, const float* __restrict__ Wsf2,
            const float* __restrict__ Wmus, const float* __restrict__ Marm,
            float* __restrict__ out)
{
    extern __shared__ float sm[];
    float* AUX   = sm;            // 64 (A fb stage + C)
    float* bias  = sm + 64;       // 128
    float* Win_s = sm + 192;      // 1200 (A only)
    float* W     = sm + 1392;     // 51200, 512 pitch

    const int tid  = threadIdx.x;
    const int lane = tid & 31;
    const int wrp  = tid >> 5;
    const int bid  = blockIdx.x;
    const int g    = bid >> 4;
    const int loc  = bid & 15;
    const int b    = g;

    u32* c_h1a = &g_cnt[g][0][0];
    u32* c_h1b = &g_cnt[g][1][0];
    u32* c_h2a = &g_cnt[g][2][0];
    u32* c_h2c = &g_cnt[g][3][0];
    u32* c_m   = &g_cnt[g][4][0];

    const float4* Wv = (const float4*)W;
    const int rbase = (wrp * 100) / 12;
    const int nr    = ((wrp + 1) * 100) / 12 - rbase;
    const int grow0 = rbase + lane;            // finalized row (lane<nr)

    if (loc < 5) {
        // ============================ A: h1 =================================
        const int r0 = loc * 100;
        const float h0 = home[b * 2], h1v = home[b * 2 + 1];
        for (int i = tid; i < 51200; i += NTHR) {
            int r = i >> 9, k = i & 511;
            W[i] = (k < 500) ? Wsf1[(r0 + r) * 500 + k] : 0.f;
        }
        for (int i = tid; i < 1200; i += NTHR)
            Win_s[i] = Win[(r0 + i / 12) * 12 + (i % 12)];
        for (int i = tid; i < 100; i += NTHR) bias[i] = bin[r0 + i];
        __syncthreads();

        float4 wreg[9][3];
        #pragma unroll
        for (int r = 0; r < 9; r++) {
            int rl = rbase + r; if (rl > 99) rl = 99;
            #pragma unroll
            for (int c = 0; c < 3; c++)
                wreg[r][c] = Wv[rl * 128 + lane + 32 * c];
        }

        if (tid < 100) g_h1[g][0][r0 + tid] = tanhf(bias[tid]);   // h1(0)
        __syncthreads();
        if (tid == 0) { redrel(c_h1a); redrel(c_h1b); }

        for (int t = 1; t < TT; ++t) {
            float nse = 0.f;
            if (lane < nr)
                nse = n1g[(size_t)(t - 1) * 4500 + b * 500 + (r0 + grow0)];

            if (tid == 0) {
                int tm = t - 6; if (tm < 0) tm = 0;
                u32 w1 = 5u * (u32)t, w2 = (u32)(tm + 1);
                for (;;) {
                    u32 a = ldacq(c_h1a);
                    u32 c = ldacq(c_m);
                    if (a >= w1 && c >= w2) break;
                }
            }
            __syncthreads();

            const float4* Xr = (const float4*)g_h1[g][(t - 1) & 7];
            float4 x0 = __ldcg(Xr + lane);
            float4 x1 = __ldcg(Xr + lane + 32);
            float4 x2 = __ldcg(Xr + lane + 64);
            float4 x3 = __ldcg(Xr + lane + 96);
            float hp = 0.f;
            if (lane < nr) hp = __ldcg(&g_h1[g][(t - 1) & 7][r0 + grow0]);

            // feedback scalars (uniform loads, per warp)
            int t6 = t - 6; if (t6 < 0) t6 = 0;
            const float* fb = g_fb[g][t6 & 7];
            float m0 = __ldcg(fb + 0), m1 = __ldcg(fb + 1), m2 = __ldcg(fb + 2);
            float m3 = __ldcg(fb + 3), m4 = __ldcg(fb + 4), m5 = __ldcg(fb + 5);
            float jp0 = 2.0f * (__ldcg(fb + 6) - h0);
            float jp1 = 2.0f * (__ldcg(fb + 7) - h1v);
            float jv0 = 0.5f * __ldcg(fb + 8);
            float jv1 = 0.5f * __ldcg(fb + 9);

            float v = gemv_rw(wreg, Wv, rbase, lane, x0, x1, x2, x3);
            if (lane < nr) {
                const float* wi = Win_s + grow0 * 12;
                float pre = v + bias[grow0]
                          + wi[2] * jp0 + wi[3] * jp1
                          + wi[4] * jv0 + wi[5] * jv1
                          + wi[6] * m0  + wi[7] * m1 + wi[8] * m2
                          + wi[9] * m3  + wi[10] * m4 + wi[11] * m5;
                g_h1[g][t & 7][r0 + grow0] =
                    0.5f * tanhf(pre) + 0.5f * hp + nse * hp * hp;
            }
            __syncthreads();
            if (tid == 0) { redrel(c_h1a); redrel(c_h1b); }
        }
    } else if (loc < 10) {
        // ============================ B1: Wout @ h1 =========================
        const int i1 = loc - 5;
        const int r0 = i1 * 100;
        u32* c_p1 = &g_cnt[g][5 + i1][0];
        for (int i = tid; i < 51200; i += NTHR) {
            int r = i >> 9, k = i & 511;
            W[i] = (k < 500) ? Wout[(r0 + r) * 500 + k] : 0.f;
        }
        __syncthreads();
        float4 wreg[9][3];
        #pragma unroll
        for (int r = 0; r < 9; r++) {
            int rl = rbase + r; if (rl > 99) rl = 99;
            #pragma unroll
            for (int c = 0; c < 3; c++)
                wreg[r][c] = Wv[rl * 128 + lane + 32 * c];
        }

        for (int t = 0; t < TT; ++t) {
            if (tid == 0) {
                u32 w1 = 5u * (u32)(t + 1);
                while (ldacq(c_h1b) < w1) { }
            }
            __syncthreads();

            const float4* Xr = (const float4*)g_h1[g][t & 7];
            float4 x0 = __ldcg(Xr + lane);
            float4 x1 = __ldcg(Xr + lane + 32);
            float4 x2 = __ldcg(Xr + lane + 64);
            float4 x3 = __ldcg(Xr + lane + 96);

            float v = gemv_rw(wreg, Wv, rbase, lane, x0, x1, x2, x3);
            if (lane < nr)
                g_p1[g][t & 7][r0 + grow0] = v;
            __syncthreads();
            if (tid == 0) redrel(c_p1);
        }
    } else if (loc < 15) {
        // ============================ B2: h2 recurrence =====================
        const int i2 = loc - 10;
        const int r0 = i2 * 100;
        u32* c_p1 = &g_cnt[g][5 + i2][0];
        for (int i = tid; i < 51200; i += NTHR) {
            int r = i >> 9, k = i & 511;
            W[i] = (k < 500) ? Wsf2[(r0 + r) * 500 + k] : 0.f;
        }
        for (int i = tid; i < 100; i += NTHR) bias[i] = bout[r0 + i];
        __syncthreads();
        float4 wreg[9][3];
        #pragma unroll
        for (int r = 0; r < 9; r++) {
            int rl = rbase + r; if (rl > 99) rl = 99;
            #pragma unroll
            for (int c = 0; c < 3; c++)
                wreg[r][c] = Wv[rl * 128 + lane + 32 * c];
        }

        for (int t = 0; t < TT; ++t) {
            float nse = 0.f;
            if (t >= 1 && lane < nr)
                nse = n2g[(size_t)(t - 1) * 4500 + b * 500 + (r0 + grow0)];

            if (tid == 0) {
                u32 w1 = (u32)(t + 1);
                u32 w2 = 5u * (u32)t;
                for (;;) {
                    u32 a = ldacq(c_p1);
                    u32 c = ldacq(c_h2a);
                    if (a >= w1 && c >= w2) break;
                }
            }
            __syncthreads();

            const float4* Xr = (const float4*)g_h2[g][(t - 1) & 7];
            float4 x0 = __ldcg(Xr + lane);
            float4 x1 = __ldcg(Xr + lane + 32);
            float4 x2 = __ldcg(Xr + lane + 64);
            float4 x3 = __ldcg(Xr + lane + 96);
            float par = 0.f, hp = 0.f;
            if (lane < nr) {
                par = __ldcg(&g_p1[g][t & 7][r0 + grow0]);
                hp  = __ldcg(&g_h2[g][(t - 1) & 7][r0 + grow0]);
            }

            float v = gemv_rw(wreg, Wv, rbase, lane, x0, x1, x2, x3);
            if (lane < nr) {
                float pre = v + par + bias[grow0];
                float val;
                if (t == 0) {
                    val = tanhf(pre);
                } else {
                    val = 0.5f * tanhf(pre) + 0.5f * hp + nse * hp * hp;
                }
                g_h2[g][t & 7][r0 + grow0] = val;
            }
            __syncthreads();
            if (tid == 0) { redrel(c_h2a); redrel(c_h2c); }
        }
    } else {
        // ============================ C: muscles + arm ======================
        for (int i = tid; i < 6 * 512; i += NTHR) {
            int r = i >> 9, k = i & 511;
            W[i] = (k < 500) ? Wmus[r * 500 + k] : 0.f;
        }
        if (tid < 12) AUX[32 + tid] = Marm[tid];
        if (tid < 2)  AUX[48 + tid] = home[b * 2 + tid];
        __syncthreads();
        if (wrp != 0) return;     // only warp 0 works

        const float4* Wvc = (const float4*)W;
        for (int t = 0; t < TT; ++t) {
            float nse = 0.f, pse = 0.f;
            if (t >= 1) {
                if (lane < 6) nse = nmg[(size_t)(t - 1) * 54 + b * 6 + lane];
                if (lane < 2) pse = pert[(size_t)(t - 1) * 18 + b * 2 + lane];
            }

            if (lane == 0) {
                u32 w1 = 5u * (u32)(t + 1);
                while (ldacq(c_h2c) < w1) { }
            }
            __syncwarp();

            const float4* Xr = (const float4*)g_h2[g][t & 7];
            float4 xs[4];
            #pragma unroll
            for (int it = 0; it < 4; ++it) xs[it] = __ldcg(Xr + lane + 32 * it);
            float acc[6];
            #pragma unroll
            for (int r = 0; r < 6; r++) acc[r] = 0.f;
            #pragma unroll
            for (int it = 0; it < 4; ++it) {
                int ch = lane + 32 * it;
                #pragma unroll
                for (int r = 0; r < 6; r++)
                    acc[r] += dot4(Wvc[r * 128 + ch], xs[it]);
            }
            bfly<6>(acc);
            float v = sel<6>(acc, lane);
            if (lane < 6) {
                float dot = fmaxf(v, 0.f);
                float mv;
                if (t == 0) {
                    mv = dot;
                } else {
                    float mp = AUX[8 + lane];
                    mv = 0.2f * dot + 0.8f * mp + nse * mp * mp;
                }
                AUX[8 + lane] = mv;
                g_fb[g][t & 7][lane] = mv;
            }
            __syncwarp();
            if (lane < 2) {
                int d = lane;
                float pos, vel;
                if (t == 0) {
                    pos = AUX[48 + d];
                    vel = 0.f;
                } else {
                    float tq = pse;
                    #pragma unroll
                    for (int j = 0; j < 6; j++)
                        tq += AUX[8 + j] * AUX[32 + j * 2 + d];
                    vel = AUX[2 + d] + 0.01f * tq;
                    pos = AUX[0 + d] + 0.01f * vel;
                }
                AUX[0 + d] = pos;
                AUX[2 + d] = vel;
                out[t * 36 + b * 4 + d]     = pos;
                out[t * 36 + b * 4 + 2 + d] = vel;
                g_fb[g][t & 7][6 + d] = pos;
                g_fb[g][t & 7][8 + d] = vel;
            }
            __syncwarp();
            if (lane == 0) redrel(c_m);
        }
    }
}

extern "C" void kernel_launch(void* const* d_in, const int* in_sizes, int n_in,
                              void* d_out, int out_size) {
    // 0 des_targ (dead: scaled by 0), 1 perturb_seq, 2 noise_h1, 3 noise_h2,
    // 4 noise_m, 5 home, 6 W_in, 7 b_in, 8 W_in_self, 9 W_out, 10 b_out,
    // 11 W_out_self, 12 W_mus, 13 M_arm
    const float* pert = (const float*)d_in[1];
    const float* n1g  = (const float*)d_in[2];
    const float* n2g  = (const float*)d_in[3];
    const float* nmg  = (const float*)d_in[4];
    const float* home = (const float*)d_in[5];
    const float* Win  = (const float*)d_in[6];
    const float* bin  = (const float*)d_in[7];
    const float* Wsf1 = (const float*)d_in[8];
    const float* Wout = (const float*)d_in[9];
    const float* bout = (const float*)d_in[10];
    const float* Wsf2 = (const float*)d_in[11];
    const float* Wmus = (const float*)d_in[12];
    const float* Marm = (const float*)d_in[13];
    float* out = (float*)d_out;

    void *p;
    cudaGetSymbolAddress(&p, g_h1);  cudaMemsetAsync(p, 0, sizeof(g_h1),  0);
    cudaGetSymbolAddress(&p, g_h2);  cudaMemsetAsync(p, 0, sizeof(g_h2),  0);
    cudaGetSymbolAddress(&p, g_p1);  cudaMemsetAsync(p, 0, sizeof(g_p1),  0);
    cudaGetSymbolAddress(&p, g_fb);  cudaMemsetAsync(p, 0, sizeof(g_fb),  0);
    cudaGetSymbolAddress(&p, g_cnt); cudaMemsetAsync(p, 0, sizeof(g_cnt), 0);

    cudaFuncSetAttribute(ctrl_kernel,
                         cudaFuncAttributeMaxDynamicSharedMemorySize, SMEMB);

    ctrl_kernel<<<GRIDN, NTHR, SMEMB, 0>>>(pert, n1g, n2g, nmg, home,
                                           Win, bin, Wsf1, Wout, bout,
                                           Wsf2, Wmus, Marm, out);
}

// round 15
// speedup vs baseline: 2.1078x; 2.0966x over previous
#include <cuda_runtime.h>
#include <math.h>

#define TT     4096
#define NTHR   384
#define GRIDN  144            // 9 batches x (A:5, B1:5, B2:5, C:1)
#define SMEMB  212416

// depth-8 L2 rings, batch-partitioned
__device__ float    g_h1[9][8][512];
__device__ float    g_h2[9][8][512];
__device__ float    g_p1[9][8][512];   // B1 partials (Wout @ h1)
__device__ float    g_fb[9][8][16];    // m[0..5], pos[6..7], vel[8..9]
__device__ unsigned g_cnt[9 * 128];    // per batch: c_h1@0 c_h2@8 c_m@16 c_p1[i]@24+8i

__device__ __forceinline__ unsigned ldacq(const unsigned* p) {
    unsigned v;
    asm volatile("ld.acquire.gpu.global.u32 %0, [%1];" : "=r"(v) : "l"(p));
    return v;
}
__device__ __forceinline__ void redrel(unsigned* p) {
    asm volatile("red.release.gpu.global.add.u32 [%0], 1;" :: "l"(p));
}

template <int N>
__device__ __forceinline__ void bfly(float* a) {
    #pragma unroll
    for (int o = 16; o; o >>= 1)
        #pragma unroll
        for (int q = 0; q < N; q++) a[q] += __shfl_xor_sync(0xffffffffu, a[q], o);
}
template <int N>
__device__ __forceinline__ float sel(const float* a, int lane) {
    float v = 0.f;
    #pragma unroll
    for (int q = 0; q < N; q++) if (lane == q) v = a[q];
    return v;
}

__device__ __forceinline__ float dot4(float4 w, float4 x) {
    return w.x * x.x + w.y * x.y + w.z * x.z + w.w * x.w;
}

// 9-row GEMV, 3/4 of W in registers, chunk 3 from SMEM. X in registers (x0..x3).
__device__ __forceinline__ float gemv_rw(const float4 wreg[9][3], const float4* Wv,
                                         int rbase, int lane,
                                         float4 x0, float4 x1, float4 x2, float4 x3) {
    float acc[9];
    #pragma unroll
    for (int r = 0; r < 9; r++) {
        int rl = rbase + r; if (rl > 99) rl = 99;
        float4 w3 = Wv[rl * 128 + lane + 96];
        acc[r] = dot4(wreg[r][0], x0) + dot4(wreg[r][1], x1)
               + dot4(wreg[r][2], x2) + dot4(w3, x3);
    }
    bfly<9>(acc);
    return sel<9>(acc, lane);
}

__global__ void __launch_bounds__(NTHR, 1)
ctrl_kernel(const float* __restrict__ pert,
            const float* __restrict__ n1g,  const float* __restrict__ n2g,
            const float* __restrict__ nmg,  const float* __restrict__ home,
            const float* __restrict__ Win,  const float* __restrict__ bin,
            const float* __restrict__ Wsf1, const float* __restrict__ Wout,
            const float* __restrict__ bout, const float* __restrict__ Wsf2,
            const float* __restrict__ Wmus, const float* __restrict__ Marm,
            float* __restrict__ out)
{
    extern __shared__ float sm[];
    float* AUX   = sm;            // 64 (C only)
    float* bias  = sm + 64;       // 128
    float* Win_s = sm + 192;      // 1200 (A only)
    float* W     = sm + 1392;     // 51200, 512 pitch

    const int tid  = threadIdx.x;
    const int lane = tid & 31;
    const int wrp  = tid >> 5;
    const int bid  = blockIdx.x;
    const int g    = bid >> 4;
    const int loc  = bid & 15;
    const int b    = g;

    unsigned* cb   = &g_cnt[g * 128];
    unsigned* c_h1 = cb;
    unsigned* c_h2 = cb + 8;
    unsigned* c_m  = cb + 16;

    const float4* Wv = (const float4*)W;
    const int rbase = (wrp * 100) / 12;
    const int nr    = ((wrp + 1) * 100) / 12 - rbase;
    const int grow0 = rbase + lane;            // finalized row (lane<nr)

    if (loc < 5) {
        // ============================ A: h1 =================================
        const int r0 = loc * 100;
        const float h0 = home[b * 2], h1v = home[b * 2 + 1];
        for (int i = tid; i < 51200; i += NTHR) {
            int r = i >> 9, k = i & 511;
            W[i] = (k < 500) ? Wsf1[(r0 + r) * 500 + k] : 0.f;
        }
        for (int i = tid; i < 1200; i += NTHR)
            Win_s[i] = Win[(r0 + i / 12) * 12 + (i % 12)];
        for (int i = tid; i < 100; i += NTHR) bias[i] = bin[r0 + i];
        if (tid < 2) AUX[32 + tid] = home[b * 2 + tid];
        __syncthreads();

        float4 wreg[9][3];
        #pragma unroll
        for (int r = 0; r < 9; r++) {
            int rl = rbase + r; if (rl > 99) rl = 99;
            #pragma unroll
            for (int c = 0; c < 3; c++)
                wreg[r][c] = Wv[rl * 128 + lane + 32 * c];
        }

        if (tid < 100) g_h1[g][0][r0 + tid] = tanhf(bias[tid]);   // h1(0)
        __syncthreads();
        if (tid == 0) redrel(c_h1);

        for (int t = 1; t < TT; ++t) {
            float nse = 0.f;
            if (lane < nr)
                nse = n1g[(size_t)(t - 1) * 4500 + b * 500 + (r0 + grow0)];

            if (tid == 0) {
                int tm = t - 6; if (tm < 0) tm = 0;
                unsigned w1 = 5u * (unsigned)t, w2 = (unsigned)(tm + 1);
                for (;;) {
                    unsigned a = ldacq(c_h1);
                    unsigned c = ldacq(c_m);
                    if (a >= w1 && c >= w2) break;
                }
            }
            __syncthreads();

            const float4* Xr = (const float4*)g_h1[g][(t - 1) & 7];
            float4 x0 = __ldcg(Xr + lane);
            float4 x1 = __ldcg(Xr + lane + 32);
            float4 x2 = __ldcg(Xr + lane + 64);
            float4 x3 = __ldcg(Xr + lane + 96);
            float hp = 0.f;
            if (lane < nr) hp = __ldcg(&g_h1[g][(t - 1) & 7][r0 + grow0]);
            if (tid < 12) {
                int c = tid;
                int t6 = t - 6; if (t6 < 0) t6 = 0;
                const float* fb = g_fb[g][t6 & 7];
                float v = 0.f;
                if (c >= 2 && c < 4)      v = 2.0f * (__ldcg(fb + 6 + (c - 2)) - AUX[32 + (c - 2)]);
                else if (c >= 4 && c < 6) v = 0.5f * __ldcg(fb + 8 + (c - 4));
                else if (c >= 6)          v = __ldcg(fb + (c - 6));
                AUX[c] = v;
            }

            float v = gemv_rw(wreg, Wv, rbase, lane, x0, x1, x2, x3);
            __syncthreads();                       // AUX ready for all

            if (lane < nr) {
                int rl = grow0;
                float pre = v + bias[rl];
                #pragma unroll
                for (int c = 0; c < 12; c++)
                    pre += Win_s[rl * 12 + c] * AUX[c];
                g_h1[g][t & 7][r0 + rl] =
                    0.5f * tanhf(pre) + 0.5f * hp + nse * hp * hp;
            }
            __syncthreads();
            if (tid == 0) redrel(c_h1);
        }
    } else if (loc < 10) {
        // ============================ B1: Wout @ h1 =========================
        const int i1 = loc - 5;
        const int r0 = i1 * 100;
        unsigned* c_p1 = cb + 24 + 8 * i1;
        for (int i = tid; i < 51200; i += NTHR) {
            int r = i >> 9, k = i & 511;
            W[i] = (k < 500) ? Wout[(r0 + r) * 500 + k] : 0.f;
        }
        __syncthreads();
        float4 wreg[9][3];
        #pragma unroll
        for (int r = 0; r < 9; r++) {
            int rl = rbase + r; if (rl > 99) rl = 99;
            #pragma unroll
            for (int c = 0; c < 3; c++)
                wreg[r][c] = Wv[rl * 128 + lane + 32 * c];
        }
        __syncthreads();

        for (int t = 0; t < TT; ++t) {
            if (tid == 0) {
                unsigned w1 = 5u * (unsigned)(t + 1);
                while (ldacq(c_h1) < w1) { }
            }
            __syncthreads();

            const float4* Xr = (const float4*)g_h1[g][t & 7];
            float4 x0 = __ldcg(Xr + lane);
            float4 x1 = __ldcg(Xr + lane + 32);
            float4 x2 = __ldcg(Xr + lane + 64);
            float4 x3 = __ldcg(Xr + lane + 96);

            float v = gemv_rw(wreg, Wv, rbase, lane, x0, x1, x2, x3);
            if (lane < nr)
                g_p1[g][t & 7][r0 + grow0] = v;
            __syncthreads();
            if (tid == 0) redrel(c_p1);
        }
    } else if (loc < 15) {
        // ============================ B2: h2 recurrence =====================
        const int i2 = loc - 10;
        const int r0 = i2 * 100;
        unsigned* c_p1 = cb + 24 + 8 * i2;
        for (int i = tid; i < 51200; i += NTHR) {
            int r = i >> 9, k = i & 511;
            W[i] = (k < 500) ? Wsf2[(r0 + r) * 500 + k] : 0.f;
        }
        for (int i = tid; i < 100; i += NTHR) bias[i] = bout[r0 + i];
        __syncthreads();
        float4 wreg[9][3];
        #pragma unroll
        for (int r = 0; r < 9; r++) {
            int rl = rbase + r; if (rl > 99) rl = 99;
            #pragma unroll
            for (int c = 0; c < 3; c++)
                wreg[r][c] = Wv[rl * 128 + lane + 32 * c];
        }
        __syncthreads();

        for (int t = 0; t < TT; ++t) {
            float nse = 0.f;
            if (t >= 1 && lane < nr)
                nse = n2g[(size_t)(t - 1) * 4500 + b * 500 + (r0 + grow0)];

            if (tid == 0) {
                unsigned w1 = (unsigned)(t + 1);
                unsigned w2 = 5u * (unsigned)t;
                for (;;) {
                    unsigned a = ldacq(c_p1);
                    unsigned c = ldacq(c_h2);
                    if (a >= w1 && c >= w2) break;
                }
            }
            __syncthreads();

            const float4* Xr = (const float4*)g_h2[g][(t - 1) & 7];
            float4 x0 = __ldcg(Xr + lane);
            float4 x1 = __ldcg(Xr + lane + 32);
            float4 x2 = __ldcg(Xr + lane + 64);
            float4 x3 = __ldcg(Xr + lane + 96);
            float par = 0.f, hp = 0.f;
            if (lane < nr) {
                par = __ldcg(&g_p1[g][t & 7][r0 + grow0]);
                hp  = __ldcg(&g_h2[g][(t - 1) & 7][r0 + grow0]);
            }

            float v = gemv_rw(wreg, Wv, rbase, lane, x0, x1, x2, x3);
            if (lane < nr) {
                float pre = v + par + bias[grow0];
                float val;
                if (t == 0) {
                    val = tanhf(pre);
                } else {
                    val = 0.5f * tanhf(pre) + 0.5f * hp + nse * hp * hp;
                }
                g_h2[g][t & 7][r0 + grow0] = val;
            }
            __syncthreads();
            if (tid == 0) redrel(c_h2);
        }
    } else {
        // ============================ C: muscles + arm ======================
        for (int i = tid; i < 6 * 512; i += NTHR) {
            int r = i >> 9, k = i & 511;
            W[i] = (k < 500) ? Wmus[r * 500 + k] : 0.f;
        }
        if (tid < 12) AUX[32 + tid] = Marm[tid];
        if (tid < 2)  AUX[48 + tid] = home[b * 2 + tid];
        __syncthreads();

        for (int t = 0; t < TT; ++t) {
            float nse = 0.f, pse = 0.f;
            if (t >= 1 && wrp == 0) {
                if (lane < 6) nse = nmg[(size_t)(t - 1) * 54 + b * 6 + lane];
                if (lane < 2) pse = pert[(size_t)(t - 1) * 18 + b * 2 + lane];
            }

            if (tid == 0) {
                unsigned w1 = 5u * (unsigned)(t + 1);
                while (ldacq(c_h2) < w1) { }
            }
            __syncthreads();

            if (wrp == 0) {
                const float4* Xr = (const float4*)g_h2[g][t & 7];
                float4 xs[4];
                #pragma unroll
                for (int it = 0; it < 4; ++it) xs[it] = __ldcg(Xr + lane + 32 * it);
                float acc[6];
                #pragma unroll
                for (int r = 0; r < 6; r++) acc[r] = 0.f;
                #pragma unroll
                for (int it = 0; it < 4; ++it) {
                    int ch = lane + 32 * it;
                    #pragma unroll
                    for (int r = 0; r < 6; r++)
                        acc[r] += dot4(Wv[r * 128 + ch], xs[it]);
                }
                bfly<6>(acc);
                float v = sel<6>(acc, lane);
                if (lane < 6) {
                    float dot = fmaxf(v, 0.f);
                    float mv;
                    if (t == 0) {
                        mv = dot;
                    } else {
                        float mp = AUX[8 + lane];
                        mv = 0.2f * dot + 0.8f * mp + nse * mp * mp;
                    }
                    AUX[8 + lane] = mv;
                    g_fb[g][t & 7][lane] = mv;
                }
                __syncwarp();
                if (lane < 2) {
                    int d = lane;
                    float pos, vel;
                    if (t == 0) {
                        pos = AUX[48 + d];
                        vel = 0.f;
                    } else {
                        float tq = pse;
                        #pragma unroll
                        for (int j = 0; j < 6; j++)
                            tq += AUX[8 + j] * AUX[32 + j * 2 + d];
                        vel = AUX[2 + d] + 0.01f * tq;
                        pos = AUX[0 + d] + 0.01f * vel;
                    }
                    AUX[0 + d] = pos;
                    AUX[2 + d] = vel;
                    out[t * 36 + b * 4 + d]     = pos;
                    out[t * 36 + b * 4 + 2 + d] = vel;
                    g_fb[g][t & 7][6 + d] = pos;
                    g_fb[g][t & 7][8 + d] = vel;
                }
            }
            __syncthreads();
            if (tid == 0) redrel(c_m);
        }
    }
}

extern "C" void kernel_launch(void* const* d_in, const int* in_sizes, int n_in,
                              void* d_out, int out_size) {
    // 0 des_targ (dead: scaled by 0), 1 perturb_seq, 2 noise_h1, 3 noise_h2,
    // 4 noise_m, 5 home, 6 W_in, 7 b_in, 8 W_in_self, 9 W_out, 10 b_out,
    // 11 W_out_self, 12 W_mus, 13 M_arm
    const float* pert = (const float*)d_in[1];
    const float* n1g  = (const float*)d_in[2];
    const float* n2g  = (const float*)d_in[3];
    const float* nmg  = (const float*)d_in[4];
    const float* home = (const float*)d_in[5];
    const float* Win  = (const float*)d_in[6];
    const float* bin  = (const float*)d_in[7];
    const float* Wsf1 = (const float*)d_in[8];
    const float* Wout = (const float*)d_in[9];
    const float* bout = (const float*)d_in[10];
    const float* Wsf2 = (const float*)d_in[11];
    const float* Wmus = (const float*)d_in[12];
    const float* Marm = (const float*)d_in[13];
    float* out = (float*)d_out;

    void *p;
    cudaGetSymbolAddress(&p, g_h1);  cudaMemsetAsync(p, 0, sizeof(g_h1),  0);
    cudaGetSymbolAddress(&p, g_h2);  cudaMemsetAsync(p, 0, sizeof(g_h2),  0);
    cudaGetSymbolAddress(&p, g_p1);  cudaMemsetAsync(p, 0, sizeof(g_p1),  0);
    cudaGetSymbolAddress(&p, g_fb);  cudaMemsetAsync(p, 0, sizeof(g_fb),  0);
    cudaGetSymbolAddress(&p, g_cnt); cudaMemsetAsync(p, 0, sizeof(g_cnt), 0);

    cudaFuncSetAttribute(ctrl_kernel,
                         cudaFuncAttributeMaxDynamicSharedMemorySize, SMEMB);

    ctrl_kernel<<<GRIDN, NTHR, SMEMB, 0>>>(pert, n1g, n2g, nmg, home,
                                           Win, bin, Wsf1, Wout, bout,
                                           Wsf2, Wmus, Marm, out);
}